// round 7
// baseline (speedup 1.0000x reference)
#include <cuda_runtime.h>
#include <cuda_fp16.h>
#include <cuda_bf16.h>

// Problem constants (fixed by reference setup_inputs):
//   src_feat [50000,128] f32, dst_feat [50000,128] f32,
//   att_w [256,1] f32, att_b [1] f32,
//   edge_index [2,640000] int32, n_dst scalar (derived from out_size).
#define DIMS 128
#define NMAX 53248     // slack over 50000, multiple of 4096
#define EMAX 700000
#define SCAN_TILE 4096

__device__ float g_srcdot[NMAX];
__device__ float g_dstdot[NMAX];                 // includes +bias
__device__ __align__(16) int g_counts[NMAX];
__device__ __align__(16) int g_offsets[NMAX + 4];
__device__ __align__(16) int g_cursor[NMAX];
__device__ int2  g_pack[EMAX];                   // {src index, att bits}
// fp16 mirror of src_feat: row-major, lane l owns halves [4l, 4l+4) as uint2.
__device__ __align__(16) uint2 g_srch[(size_t)NMAX * 32];

// ---------------------------------------------------------------------------
// K1: fused per-row dots (4 rows/warp, weights loaded once) + histogram.
// Src-row warps additionally write the fp16 mirror of their rows.
// ---------------------------------------------------------------------------
__global__ void prep_kernel(const float* __restrict__ src_feat,
                            const float* __restrict__ dst_feat,
                            const float* __restrict__ att_w,
                            const float* __restrict__ att_b,
                            const int* __restrict__ edge_index,
                            int n_src, int n_dst, int n_edges,
                            int dot_blocks) {
    if (blockIdx.x < (unsigned)dot_blocks) {
        int gw   = (blockIdx.x * blockDim.x + threadIdx.x) >> 5;
        int lane = threadIdx.x & 31;
        int total = n_src + n_dst;
        int base = gw * 4;
        if (base >= total) return;

        float4 wv_s = ((const float4*)att_w)[lane];
        float4 wv_d = ((const float4*)(att_w + DIMS))[lane];
        float bias = att_b[0];

        // Issue all 4 feature-row loads up front (MLP=4).
        float4 f[4];
        #pragma unroll
        for (int r = 0; r < 4; r++) {
            int row = base + r;
            if (row < total) {
                const float* feat = (row < n_src)
                    ? (src_feat + (size_t)row * DIMS)
                    : (dst_feat + (size_t)(row - n_src) * DIMS);
                f[r] = ((const float4*)feat)[lane];
            } else {
                f[r] = make_float4(0.f, 0.f, 0.f, 0.f);
            }
        }

        #pragma unroll
        for (int r = 0; r < 4; r++) {
            int row = base + r;
            if (row >= total) break;
            bool is_src = (row < n_src);

            if (is_src) {
                // fp16 mirror: 4 floats -> 2x half2 packed in a uint2.
                __half2 h01 = __floats2half2_rn(f[r].x, f[r].y);
                __half2 h23 = __floats2half2_rn(f[r].z, f[r].w);
                uint2 hv;
                hv.x = *(unsigned int*)&h01;
                hv.y = *(unsigned int*)&h23;
                g_srch[(size_t)row * 32 + lane] = hv;
            }

            float4 wv = is_src ? wv_s : wv_d;
            float s = f[r].x * wv.x + f[r].y * wv.y
                    + f[r].z * wv.z + f[r].w * wv.w;
            #pragma unroll
            for (int o = 16; o > 0; o >>= 1)
                s += __shfl_down_sync(0xffffffffu, s, o);
            if (lane == 0) {
                if (is_src) g_srcdot[row] = s;
                else        g_dstdot[row - n_src] = s + bias;
            }
        }
    } else {
        int i = (blockIdx.x - dot_blocks) * blockDim.x + threadIdx.x;
        if (i >= n_edges) return;
        atomicAdd(&g_counts[edge_index[n_edges + i]], 1);
    }
}

// ---------------------------------------------------------------------------
// K2: single-kernel scan (redundant coalesced prefix per block).
// ---------------------------------------------------------------------------
__global__ void scan_kernel(int n_dst, int n_tiles) {
    __shared__ int wsum[32];
    __shared__ int s_prefix;
    int b = blockIdx.x, t = threadIdx.x;
    int lane = t & 31, w = t >> 5;
    int nwarps = blockDim.x >> 5;

    int pre = 0;
    {
        int limit4 = (b * SCAN_TILE) >> 2;
        const int4* c4 = (const int4*)g_counts;
        for (int i = t; i < limit4; i += blockDim.x) {
            int4 v = c4[i];
            pre += v.x + v.y + v.z + v.w;
        }
        #pragma unroll
        for (int o = 16; o > 0; o >>= 1)
            pre += __shfl_down_sync(0xffffffffu, pre, o);
        if (lane == 0) wsum[w] = pre;
        __syncthreads();
        if (w == 0) {
            int v = (lane < nwarps) ? wsum[lane] : 0;
            #pragma unroll
            for (int o = 16; o > 0; o >>= 1)
                v += __shfl_down_sync(0xffffffffu, v, o);
            if (lane == 0) s_prefix = v;
        }
        __syncthreads();
    }
    int tile_prefix = s_prefix;
    __syncthreads();

    int base = b * SCAN_TILE + t * 4;
    int4 v = make_int4(0, 0, 0, 0);
    if (base + 3 < n_dst) {
        v = *(const int4*)&g_counts[base];
    } else {
        if (base + 0 < n_dst) v.x = g_counts[base + 0];
        if (base + 1 < n_dst) v.y = g_counts[base + 1];
        if (base + 2 < n_dst) v.z = g_counts[base + 2];
        if (base + 3 < n_dst) v.w = g_counts[base + 3];
    }
    int s0 = v.x, s1 = s0 + v.y, s2 = s1 + v.z, s3 = s2 + v.w;

    int incl = s3;
    #pragma unroll
    for (int o = 1; o < 32; o <<= 1) {
        int y = __shfl_up_sync(0xffffffffu, incl, o);
        if (lane >= o) incl += y;
    }
    if (lane == 31) wsum[w] = incl;
    __syncthreads();
    if (w == 0) {
        int x = (lane < nwarps) ? wsum[lane] : 0;
        #pragma unroll
        for (int o = 1; o < 32; o <<= 1) {
            int y = __shfl_up_sync(0xffffffffu, x, o);
            if (lane >= o) x += y;
        }
        wsum[lane] = x;
    }
    __syncthreads();
    int prefix = (incl - s3) + (w > 0 ? wsum[w - 1] : 0) + tile_prefix;

    int4 o4 = make_int4(prefix, prefix + s0, prefix + s1, prefix + s2);
    if (base + 3 < n_dst) {
        *(int4*)&g_offsets[base] = o4;
        *(int4*)&g_cursor[base]  = o4;
    } else {
        if (base + 0 < n_dst) { g_offsets[base + 0] = o4.x; g_cursor[base + 0] = o4.x; }
        if (base + 1 < n_dst) { g_offsets[base + 1] = o4.y; g_cursor[base + 1] = o4.y; }
        if (base + 2 < n_dst) { g_offsets[base + 2] = o4.z; g_cursor[base + 2] = o4.z; }
        if (base + 3 < n_dst) { g_offsets[base + 3] = o4.w; g_cursor[base + 3] = o4.w; }
    }

    if (b == n_tiles - 1 && t == 0)
        g_offsets[n_dst] = tile_prefix + wsum[nwarps - 1];
}

// ---------------------------------------------------------------------------
// K3: scatter edges into buckets. 4 edges per thread; packed payload.
// ---------------------------------------------------------------------------
__global__ void scatter_kernel(const int* __restrict__ edge_index, int n_edges) {
    int i0 = (blockIdx.x * blockDim.x + threadIdx.x) * 4;
    if (i0 >= n_edges) return;

    if (i0 + 4 <= n_edges && (n_edges & 3) == 0) {
        int4 s4 = *(const int4*)&edge_index[i0];
        int4 d4 = *(const int4*)&edge_index[n_edges + i0];

        float sa = g_srcdot[s4.x], sb = g_srcdot[s4.y];
        float sc = g_srcdot[s4.z], sd = g_srcdot[s4.w];
        float da = g_dstdot[d4.x], db = g_dstdot[d4.y];
        float dc = g_dstdot[d4.z], dd = g_dstdot[d4.w];

        float a0 = 1.0f / (1.0f + __expf(-(sa + da)));
        float a1 = 1.0f / (1.0f + __expf(-(sb + db)));
        float a2 = 1.0f / (1.0f + __expf(-(sc + dc)));
        float a3 = 1.0f / (1.0f + __expf(-(sd + dd)));

        int p0 = atomicAdd(&g_cursor[d4.x], 1);
        int p1 = atomicAdd(&g_cursor[d4.y], 1);
        int p2 = atomicAdd(&g_cursor[d4.z], 1);
        int p3 = atomicAdd(&g_cursor[d4.w], 1);

        g_pack[p0] = make_int2(s4.x, __float_as_int(a0));
        g_pack[p1] = make_int2(s4.y, __float_as_int(a1));
        g_pack[p2] = make_int2(s4.z, __float_as_int(a2));
        g_pack[p3] = make_int2(s4.w, __float_as_int(a3));
    } else {
        for (int i = i0; i < n_edges && i < i0 + 4; i++) {
            int s = edge_index[i];
            int d = edge_index[n_edges + i];
            float att = 1.0f / (1.0f + __expf(-(g_srcdot[s] + g_dstdot[d])));
            int pos = atomicAdd(&g_cursor[d], 1);
            g_pack[pos] = make_int2(s, __float_as_int(att));
        }
    }
}

// ---------------------------------------------------------------------------
// K4: warp-per-dst aggregation on fp16 src rows + fused normalize.
// 8-wide unroll: MLP=8 gathers of 256 B each. Accumulate in fp32.
// ---------------------------------------------------------------------------
__global__ void agg_kernel(float* __restrict__ out, int n_dst) {
    int wid  = (blockIdx.x * blockDim.x + threadIdx.x) >> 5;
    int lane = threadIdx.x & 31;
    if (wid >= n_dst) return;

    int start = g_offsets[wid];
    int end   = g_offsets[wid + 1];

    float4 acc = make_float4(0.f, 0.f, 0.f, 0.f);
    float attsum = 0.f;

    int e = start;
    for (; e + 7 < end; e += 8) {
        int2  p[8];
        uint2 hv[8];
        #pragma unroll
        for (int k = 0; k < 8; k++) p[k] = g_pack[e + k];
        #pragma unroll
        for (int k = 0; k < 8; k++)
            hv[k] = g_srch[(size_t)p[k].x * 32 + lane];
        #pragma unroll
        for (int k = 0; k < 8; k++) {
            float a = __int_as_float(p[k].y);
            float2 f01 = __half22float2(*(__half2*)&hv[k].x);
            float2 f23 = __half22float2(*(__half2*)&hv[k].y);
            acc.x = fmaf(a, f01.x, acc.x);
            acc.y = fmaf(a, f01.y, acc.y);
            acc.z = fmaf(a, f23.x, acc.z);
            acc.w = fmaf(a, f23.y, acc.w);
            attsum += a;
        }
    }
    for (; e < end; e++) {
        int2 p = g_pack[e];
        float a = __int_as_float(p.y);
        uint2 hv = g_srch[(size_t)p.x * 32 + lane];
        float2 f01 = __half22float2(*(__half2*)&hv.x);
        float2 f23 = __half22float2(*(__half2*)&hv.y);
        acc.x = fmaf(a, f01.x, acc.x);
        acc.y = fmaf(a, f01.y, acc.y);
        acc.z = fmaf(a, f23.x, acc.z);
        acc.w = fmaf(a, f23.y, acc.w);
        attsum += a;
    }

    float inv = 1.0f / fmaxf(attsum, 1e-8f);
    float4 r = make_float4(acc.x * inv, acc.y * inv, acc.z * inv, acc.w * inv);
    ((float4*)(out + (size_t)wid * DIMS))[lane] = r;
}

// ---------------------------------------------------------------------------
extern "C" void kernel_launch(void* const* d_in, const int* in_sizes, int n_in,
                              void* d_out, int out_size) {
    const float* src_feat   = (const float*)d_in[0];
    const float* dst_feat   = (const float*)d_in[1];
    const float* att_w      = (const float*)d_in[2];
    const float* att_b      = (const float*)d_in[3];
    const int*   edge_index = (const int*)d_in[4];

    int n_src   = in_sizes[0] / DIMS;
    int n_dst   = out_size    / DIMS;
    int n_edges = in_sizes[4] / 2;

    float* out = (float*)d_out;

    void* counts_ptr = nullptr;
    cudaGetSymbolAddress(&counts_ptr, g_counts);
    cudaMemsetAsync(counts_ptr, 0, (size_t)n_dst * sizeof(int), 0);

    // K1: fused dots (4 rows/warp) + fp16 staging + histogram.
    {
        int threads = 256;
        int total = n_src + n_dst;
        int dot_warps = (total + 3) / 4;
        int dot_blocks  = (dot_warps * 32 + threads - 1) / threads;
        int hist_blocks = (n_edges + threads - 1) / threads;
        prep_kernel<<<dot_blocks + hist_blocks, threads>>>(
            src_feat, dst_feat, att_w, att_b, edge_index,
            n_src, n_dst, n_edges, dot_blocks);
    }

    // K2: single-kernel scan.
    int n_tiles = (n_dst + SCAN_TILE - 1) / SCAN_TILE;
    scan_kernel<<<n_tiles, 1024>>>(n_dst, n_tiles);

    // K3: scatter (4 edges per thread).
    {
        int threads = 256;
        int blocks = (n_edges + threads * 4 - 1) / (threads * 4);
        scatter_kernel<<<blocks, threads>>>(edge_index, n_edges);
    }

    // K4: warp-per-dst aggregate on fp16 rows + normalize.
    {
        int threads = 256;
        int warps_per_block = threads / 32;
        int blocks = (n_dst + warps_per_block - 1) / warps_per_block;
        agg_kernel<<<blocks, threads>>>(out, n_dst);
    }
}

// round 9
// speedup vs baseline: 1.0697x; 1.0697x over previous
#include <cuda_runtime.h>
#include <cuda_fp16.h>
#include <cuda_bf16.h>

// Problem constants (fixed by reference setup_inputs):
//   src_feat [50000,128] f32, dst_feat [50000,128] f32,
//   att_w [256,1] f32, att_b [1] f32,
//   edge_index [2,640000] int32, n_dst scalar (derived from out_size).
#define DIMS 128
#define NMAX 53248     // slack over 50000, multiple of 4096
#define EMAX 700000
#define SCAN_TILE 4096

__device__ float g_srcdot[NMAX];
__device__ float g_dstdot[NMAX];                 // includes +bias
__device__ __align__(16) int g_counts[NMAX];
__device__ __align__(16) int g_offsets[NMAX + 4];
__device__ __align__(16) int g_cursor[NMAX];
__device__ __align__(16) int2 g_pack[EMAX];      // {src index, att bits}
// fp16 mirror of src_feat: row-major, lane l owns halves [4l, 4l+4) as uint2.
__device__ __align__(16) uint2 g_srch[(size_t)NMAX * 32];

// ---------------------------------------------------------------------------
// K1: fused per-row dots (8 rows/warp, weights loaded once) + histogram.
// Src-row warps additionally write the fp16 mirror of their rows.
// ---------------------------------------------------------------------------
__global__ void prep_kernel(const float* __restrict__ src_feat,
                            const float* __restrict__ dst_feat,
                            const float* __restrict__ att_w,
                            const float* __restrict__ att_b,
                            const int* __restrict__ edge_index,
                            int n_src, int n_dst, int n_edges,
                            int dot_blocks) {
    if (blockIdx.x < (unsigned)dot_blocks) {
        int gw   = (blockIdx.x * blockDim.x + threadIdx.x) >> 5;
        int lane = threadIdx.x & 31;
        int total = n_src + n_dst;
        int base = gw * 8;
        if (base >= total) return;

        float4 wv_s = ((const float4*)att_w)[lane];
        float4 wv_d = ((const float4*)(att_w + DIMS))[lane];
        float bias = att_b[0];

        // Issue all 8 feature-row loads up front (MLP=8).
        float4 f[8];
        #pragma unroll
        for (int r = 0; r < 8; r++) {
            int row = base + r;
            if (row < total) {
                const float* feat = (row < n_src)
                    ? (src_feat + (size_t)row * DIMS)
                    : (dst_feat + (size_t)(row - n_src) * DIMS);
                f[r] = ((const float4*)feat)[lane];
            } else {
                f[r] = make_float4(0.f, 0.f, 0.f, 0.f);
            }
        }

        #pragma unroll
        for (int r = 0; r < 8; r++) {
            int row = base + r;
            if (row >= total) break;
            bool is_src = (row < n_src);

            if (is_src) {
                __half2 h01 = __floats2half2_rn(f[r].x, f[r].y);
                __half2 h23 = __floats2half2_rn(f[r].z, f[r].w);
                uint2 hv;
                hv.x = *(unsigned int*)&h01;
                hv.y = *(unsigned int*)&h23;
                g_srch[(size_t)row * 32 + lane] = hv;
            }

            float4 wv = is_src ? wv_s : wv_d;
            float s = f[r].x * wv.x + f[r].y * wv.y
                    + f[r].z * wv.z + f[r].w * wv.w;
            #pragma unroll
            for (int o = 16; o > 0; o >>= 1)
                s += __shfl_down_sync(0xffffffffu, s, o);
            if (lane == 0) {
                if (is_src) g_srcdot[row] = s;
                else        g_dstdot[row - n_src] = s + bias;
            }
        }
    } else {
        int i = (blockIdx.x - dot_blocks) * blockDim.x + threadIdx.x;
        if (i >= n_edges) return;
        atomicAdd(&g_counts[edge_index[n_edges + i]], 1);
    }
}

// ---------------------------------------------------------------------------
// K2: single-kernel scan (redundant coalesced prefix per block).
// ---------------------------------------------------------------------------
__global__ void scan_kernel(int n_dst, int n_tiles) {
    __shared__ int wsum[32];
    __shared__ int s_prefix;
    int b = blockIdx.x, t = threadIdx.x;
    int lane = t & 31, w = t >> 5;
    int nwarps = blockDim.x >> 5;

    int pre = 0;
    {
        int limit4 = (b * SCAN_TILE) >> 2;
        const int4* c4 = (const int4*)g_counts;
        for (int i = t; i < limit4; i += blockDim.x) {
            int4 v = c4[i];
            pre += v.x + v.y + v.z + v.w;
        }
        #pragma unroll
        for (int o = 16; o > 0; o >>= 1)
            pre += __shfl_down_sync(0xffffffffu, pre, o);
        if (lane == 0) wsum[w] = pre;
        __syncthreads();
        if (w == 0) {
            int v = (lane < nwarps) ? wsum[lane] : 0;
            #pragma unroll
            for (int o = 16; o > 0; o >>= 1)
                v += __shfl_down_sync(0xffffffffu, v, o);
            if (lane == 0) s_prefix = v;
        }
        __syncthreads();
    }
    int tile_prefix = s_prefix;
    __syncthreads();

    int base = b * SCAN_TILE + t * 4;
    int4 v = make_int4(0, 0, 0, 0);
    if (base + 3 < n_dst) {
        v = *(const int4*)&g_counts[base];
    } else {
        if (base + 0 < n_dst) v.x = g_counts[base + 0];
        if (base + 1 < n_dst) v.y = g_counts[base + 1];
        if (base + 2 < n_dst) v.z = g_counts[base + 2];
        if (base + 3 < n_dst) v.w = g_counts[base + 3];
    }
    int s0 = v.x, s1 = s0 + v.y, s2 = s1 + v.z, s3 = s2 + v.w;

    int incl = s3;
    #pragma unroll
    for (int o = 1; o < 32; o <<= 1) {
        int y = __shfl_up_sync(0xffffffffu, incl, o);
        if (lane >= o) incl += y;
    }
    if (lane == 31) wsum[w] = incl;
    __syncthreads();
    if (w == 0) {
        int x = (lane < nwarps) ? wsum[lane] : 0;
        #pragma unroll
        for (int o = 1; o < 32; o <<= 1) {
            int y = __shfl_up_sync(0xffffffffu, x, o);
            if (lane >= o) x += y;
        }
        wsum[lane] = x;
    }
    __syncthreads();
    int prefix = (incl - s3) + (w > 0 ? wsum[w - 1] : 0) + tile_prefix;

    int4 o4 = make_int4(prefix, prefix + s0, prefix + s1, prefix + s2);
    if (base + 3 < n_dst) {
        *(int4*)&g_offsets[base] = o4;
        *(int4*)&g_cursor[base]  = o4;
    } else {
        if (base + 0 < n_dst) { g_offsets[base + 0] = o4.x; g_cursor[base + 0] = o4.x; }
        if (base + 1 < n_dst) { g_offsets[base + 1] = o4.y; g_cursor[base + 1] = o4.y; }
        if (base + 2 < n_dst) { g_offsets[base + 2] = o4.z; g_cursor[base + 2] = o4.z; }
        if (base + 3 < n_dst) { g_offsets[base + 3] = o4.w; g_cursor[base + 3] = o4.w; }
    }

    if (b == n_tiles - 1 && t == 0)
        g_offsets[n_dst] = tile_prefix + wsum[nwarps - 1];
}

// ---------------------------------------------------------------------------
// K3: scatter edges into buckets. 4 edges per thread; packed payload.
// ---------------------------------------------------------------------------
__global__ void scatter_kernel(const int* __restrict__ edge_index, int n_edges) {
    int i0 = (blockIdx.x * blockDim.x + threadIdx.x) * 4;
    if (i0 >= n_edges) return;

    if (i0 + 4 <= n_edges && (n_edges & 3) == 0) {
        int4 s4 = *(const int4*)&edge_index[i0];
        int4 d4 = *(const int4*)&edge_index[n_edges + i0];

        float sa = g_srcdot[s4.x], sb = g_srcdot[s4.y];
        float sc = g_srcdot[s4.z], sd = g_srcdot[s4.w];
        float da = g_dstdot[d4.x], db = g_dstdot[d4.y];
        float dc = g_dstdot[d4.z], dd = g_dstdot[d4.w];

        float a0 = 1.0f / (1.0f + __expf(-(sa + da)));
        float a1 = 1.0f / (1.0f + __expf(-(sb + db)));
        float a2 = 1.0f / (1.0f + __expf(-(sc + dc)));
        float a3 = 1.0f / (1.0f + __expf(-(sd + dd)));

        int p0 = atomicAdd(&g_cursor[d4.x], 1);
        int p1 = atomicAdd(&g_cursor[d4.y], 1);
        int p2 = atomicAdd(&g_cursor[d4.z], 1);
        int p3 = atomicAdd(&g_cursor[d4.w], 1);

        g_pack[p0] = make_int2(s4.x, __float_as_int(a0));
        g_pack[p1] = make_int2(s4.y, __float_as_int(a1));
        g_pack[p2] = make_int2(s4.z, __float_as_int(a2));
        g_pack[p3] = make_int2(s4.w, __float_as_int(a3));
    } else {
        for (int i = i0; i < n_edges && i < i0 + 4; i++) {
            int s = edge_index[i];
            int d = edge_index[n_edges + i];
            float att = 1.0f / (1.0f + __expf(-(g_srcdot[s] + g_dstdot[d])));
            int pos = atomicAdd(&g_cursor[d], 1);
            g_pack[pos] = make_int2(s, __float_as_int(att));
        }
    }
}

// ---------------------------------------------------------------------------
// K4: warp-per-dst aggregation on fp16 src rows + fused normalize.
// 4-wide unroll (pack read as 2x int4); __launch_bounds__ forces <=32 regs
// so 8 blocks/SM = 100% occupancy — latency hidden by warp count.
// ---------------------------------------------------------------------------
__global__ void __launch_bounds__(256, 8)
agg_kernel(float* __restrict__ out, int n_dst) {
    int wid  = (blockIdx.x * blockDim.x + threadIdx.x) >> 5;
    int lane = threadIdx.x & 31;
    if (wid >= n_dst) return;

    int start = g_offsets[wid];
    int end   = g_offsets[wid + 1];

    float4 acc = make_float4(0.f, 0.f, 0.f, 0.f);
    float attsum = 0.f;

    int e = start;
    // Align to int4 boundary of g_pack (2 entries per int4).
    if ((e & 1) && e < end) {
        int2 p = g_pack[e];
        float a = __int_as_float(p.y);
        uint2 hv = g_srch[(size_t)p.x * 32 + lane];
        float2 f01 = __half22float2(*(__half2*)&hv.x);
        float2 f23 = __half22float2(*(__half2*)&hv.y);
        acc.x = fmaf(a, f01.x, acc.x); acc.y = fmaf(a, f01.y, acc.y);
        acc.z = fmaf(a, f23.x, acc.z); acc.w = fmaf(a, f23.y, acc.w);
        attsum += a;
        e++;
    }
    for (; e + 3 < end; e += 4) {
        // 4 pack entries via 2 vector loads (broadcast across warp).
        int4 q0 = *(const int4*)&g_pack[e];       // {s0, a0, s1, a1}
        int4 q1 = *(const int4*)&g_pack[e + 2];   // {s2, a2, s3, a3}
        uint2 h0 = g_srch[(size_t)q0.x * 32 + lane];
        uint2 h1 = g_srch[(size_t)q0.z * 32 + lane];
        uint2 h2 = g_srch[(size_t)q1.x * 32 + lane];
        uint2 h3 = g_srch[(size_t)q1.z * 32 + lane];
        float a0 = __int_as_float(q0.y), a1 = __int_as_float(q0.w);
        float a2 = __int_as_float(q1.y), a3 = __int_as_float(q1.w);

        float2 f;
        f = __half22float2(*(__half2*)&h0.x);
        acc.x = fmaf(a0, f.x, acc.x); acc.y = fmaf(a0, f.y, acc.y);
        f = __half22float2(*(__half2*)&h0.y);
        acc.z = fmaf(a0, f.x, acc.z); acc.w = fmaf(a0, f.y, acc.w);
        f = __half22float2(*(__half2*)&h1.x);
        acc.x = fmaf(a1, f.x, acc.x); acc.y = fmaf(a1, f.y, acc.y);
        f = __half22float2(*(__half2*)&h1.y);
        acc.z = fmaf(a1, f.x, acc.z); acc.w = fmaf(a1, f.y, acc.w);
        f = __half22float2(*(__half2*)&h2.x);
        acc.x = fmaf(a2, f.x, acc.x); acc.y = fmaf(a2, f.y, acc.y);
        f = __half22float2(*(__half2*)&h2.y);
        acc.z = fmaf(a2, f.x, acc.z); acc.w = fmaf(a2, f.y, acc.w);
        f = __half22float2(*(__half2*)&h3.x);
        acc.x = fmaf(a3, f.x, acc.x); acc.y = fmaf(a3, f.y, acc.y);
        f = __half22float2(*(__half2*)&h3.y);
        acc.z = fmaf(a3, f.x, acc.z); acc.w = fmaf(a3, f.y, acc.w);
        attsum += (a0 + a1) + (a2 + a3);
    }
    for (; e < end; e++) {
        int2 p = g_pack[e];
        float a = __int_as_float(p.y);
        uint2 hv = g_srch[(size_t)p.x * 32 + lane];
        float2 f01 = __half22float2(*(__half2*)&hv.x);
        float2 f23 = __half22float2(*(__half2*)&hv.y);
        acc.x = fmaf(a, f01.x, acc.x); acc.y = fmaf(a, f01.y, acc.y);
        acc.z = fmaf(a, f23.x, acc.z); acc.w = fmaf(a, f23.y, acc.w);
        attsum += a;
    }

    float inv = 1.0f / fmaxf(attsum, 1e-8f);
    float4 r = make_float4(acc.x * inv, acc.y * inv, acc.z * inv, acc.w * inv);
    ((float4*)(out + (size_t)wid * DIMS))[lane] = r;
}

// ---------------------------------------------------------------------------
extern "C" void kernel_launch(void* const* d_in, const int* in_sizes, int n_in,
                              void* d_out, int out_size) {
    const float* src_feat   = (const float*)d_in[0];
    const float* dst_feat   = (const float*)d_in[1];
    const float* att_w      = (const float*)d_in[2];
    const float* att_b      = (const float*)d_in[3];
    const int*   edge_index = (const int*)d_in[4];

    int n_src   = in_sizes[0] / DIMS;
    int n_dst   = out_size    / DIMS;
    int n_edges = in_sizes[4] / 2;

    float* out = (float*)d_out;

    void* counts_ptr = nullptr;
    cudaGetSymbolAddress(&counts_ptr, g_counts);
    cudaMemsetAsync(counts_ptr, 0, (size_t)n_dst * sizeof(int), 0);

    // K1: fused dots (8 rows/warp) + fp16 staging + histogram.
    {
        int threads = 256;
        int total = n_src + n_dst;
        int dot_warps = (total + 7) / 8;
        int dot_blocks  = (dot_warps * 32 + threads - 1) / threads;
        int hist_blocks = (n_edges + threads - 1) / threads;
        prep_kernel<<<dot_blocks + hist_blocks, threads>>>(
            src_feat, dst_feat, att_w, att_b, edge_index,
            n_src, n_dst, n_edges, dot_blocks);
    }

    // K2: single-kernel scan.
    int n_tiles = (n_dst + SCAN_TILE - 1) / SCAN_TILE;
    scan_kernel<<<n_tiles, 1024>>>(n_dst, n_tiles);

    // K3: scatter (4 edges per thread).
    {
        int threads = 256;
        int blocks = (n_edges + threads * 4 - 1) / (threads * 4);
        scatter_kernel<<<blocks, threads>>>(edge_index, n_edges);
    }

    // K4: warp-per-dst aggregate on fp16 rows + normalize (full occupancy).
    {
        int threads = 256;
        int warps_per_block = threads / 32;
        int blocks = (n_dst + warps_per_block - 1) / warps_per_block;
        agg_kernel<<<blocks, threads>>>(out, n_dst);
    }
}